// round 6
// baseline (speedup 1.0000x reference)
#include <cuda_runtime.h>
#include <cstdint>
#include <math.h>

// ============================================================================
// Fused NeRF MLP (RadianceField), base sm_100 target (no tcgen05).
// mma.sync.m16n8k8 tf32 + ldmatrix fragments, persistent 256-thread CTAs,
// cp.async weight streaming, 2(M)x4(N) warp split.
// ============================================================================

#define NTHREADS 256
#define MTILE    128

#define ACT_S    260                        // floats/row; 1040B stride (mod128=16)
#define XB_S     64                         // swizzled rows of 256B
#define XB_OFF   (128 * ACT_S * 4)          // 133120
#define WB_OFF   (XB_OFF + 128 * XB_S * 4)  // 165888
#define WB_BYTES 32768                      // 256 rows * 32 cols * 4B
#define SMEM_TOTAL (WB_OFF + 2 * WB_BYTES)  // 231424 <= 232448 cap

#define TOT_CHUNKS 89

struct Params { const float* p[32]; };

__constant__ int c_widx[13] = {2, 4, 6, 8, 10, 12, 14, 16, 20, 22, 24, 26, 28};
__constant__ int c_kact[13] = {63, 256, 256, 256, 256, 319, 256, 256, 256, 283, 128, 128, 128};
__constant__ int c_nch [13] = { 2,   8,   8,   8,   8,  10,   8,   8,   8,   9,   4,   4,   4};

// ----------------------------------------------------------------------------
__device__ __forceinline__ uint32_t smem_u32_of(const void* p) {
    uint32_t a;
    asm("{ .reg .u64 t; cvta.to.shared.u64 t, %1; cvt.u32.u64 %0, t; }" : "=r"(a) : "l"(p));
    return a;
}

__device__ __forceinline__ uint32_t cvt_tf32(float v) {
    uint32_t r;
    asm("cvt.rna.tf32.f32 %0, %1;" : "=r"(r) : "f"(v));
    return r;
}
__device__ __forceinline__ float rnd_tf32(float v) { return __uint_as_float(cvt_tf32(v)); }

__device__ __forceinline__ void cp_async16(uint32_t dst, const void* src) {
    asm volatile("cp.async.ca.shared.global [%0], [%1], 16;" :: "r"(dst), "l"(src));
}
__device__ __forceinline__ void cp_async4(uint32_t dst, const void* src, int srcsize) {
    asm volatile("cp.async.ca.shared.global [%0], [%1], 4, %2;"
                 :: "r"(dst), "l"(src), "r"(srcsize));
}
__device__ __forceinline__ void cp_commit() { asm volatile("cp.async.commit_group;"); }
template <int N> __device__ __forceinline__ void cp_wait() {
    asm volatile("cp.async.wait_group %0;" :: "n"(N));
}

__device__ __forceinline__ void ldsm_x4(uint32_t r[4], uint32_t addr) {
    asm volatile("ldmatrix.sync.aligned.m8n8.x4.shared.b16 {%0,%1,%2,%3}, [%4];"
                 : "=r"(r[0]), "=r"(r[1]), "=r"(r[2]), "=r"(r[3]) : "r"(addr));
}
__device__ __forceinline__ void ldsm_x2(uint32_t& r0, uint32_t& r1, uint32_t addr) {
    asm volatile("ldmatrix.sync.aligned.m8n8.x2.shared.b16 {%0,%1}, [%2];"
                 : "=r"(r0), "=r"(r1) : "r"(addr));
}

__device__ __forceinline__ void mma_tf32(float c[4], uint32_t a0, uint32_t a1,
                                         uint32_t a2, uint32_t a3,
                                         uint32_t b0, uint32_t b1) {
    asm volatile(
        "mma.sync.aligned.m16n8k8.row.col.f32.tf32.tf32.f32 "
        "{%0,%1,%2,%3}, {%4,%5,%6,%7}, {%8,%9}, {%0,%1,%2,%3};"
        : "+f"(c[0]), "+f"(c[1]), "+f"(c[2]), "+f"(c[3])
        : "r"(a0), "r"(a1), "r"(a2), "r"(a3), "r"(b0), "r"(b1));
}

// Weight buffer addressing: row n (128B), 16B granule XOR-swizzled by (n&7).
__device__ __forceinline__ uint32_t wb_addr(uint32_t wb_base, int n, int k) {
    return wb_base + (uint32_t)((n * 8 + ((k >> 2) ^ (n & 7))) * 16 + (k & 3) * 4);
}
// XB addressing: row r (256B), 16B granule XOR-swizzled by (r&7). Index in floats.
__device__ __forceinline__ int xb_idx(int r, int c) {
    return r * 64 + ((((c >> 2) ^ (r & 7)) << 2) | (c & 3));
}

// ----------------------------------------------------------------------------
// Issue one weight chunk (kk..kk+31 of W[N][K]) into buffer via cp.async.
// ----------------------------------------------------------------------------
__device__ __forceinline__ void issue_chunk(const float* __restrict__ W, int K, int kk,
                                            int N, uint32_t wb_base, int tid) {
    if ((K & 3) == 0) {
        const int iters = N >> 5;
        for (int i = 0; i < iters; i++) {
            int f4 = i * NTHREADS + tid;
            int n = f4 >> 3, k4 = f4 & 7;
            const float* src = W + (size_t)n * K + kk + k4 * 4;
            uint32_t dst = wb_base + (uint32_t)((n * 8 + (k4 ^ (n & 7))) * 16);
            cp_async16(dst, src);
        }
    } else {
        const int iters = N >> 3;
        for (int i = 0; i < iters; i++) {
            int f = i * NTHREADS + tid;
            int n = f >> 5, k = f & 31;
            int kg = kk + k;
            int ss = (kg < K) ? 4 : 0;
            int kc = (kg < K) ? kg : (K - 1);
            cp_async4(wb_addr(wb_base, n, k), W + (size_t)n * K + kc, ss);
        }
    }
    cp_commit();
}

// ----------------------------------------------------------------------------
// Compute one 32-k chunk. Warp (wm, wn): rows [wm*64, +64), cols [wn*NT*8, +NT*8).
// NT = 8 (N=256) or 4 (N=128).  XBSRC: A from swizzled XB, else ACT (stride 1040B).
// ----------------------------------------------------------------------------
template <int NT, bool XBSRC>
__device__ __forceinline__ void compute_chunk(float acc[4][8][4], uint32_t abase, int cb,
                                              uint32_t wb, int lane, int wm, int wn) {
    const int rowin = lane & 7;
    const int rhalf = (lane >> 3) & 1;     // A: row half selector
    const int chalf = (lane >> 4) & 1;     // A: col +4 selector
    const int bsub  = (lane >> 3) & 1;     // B: k +4 selector (lanes 0..15 used)

#pragma unroll
    for (int k8 = 0; k8 < 4; k8++) {
        // B fragments (raw fp32 -> tf32)
        uint32_t b0[NT], b1[NT];
#pragma unroll
        for (int nt = 0; nt < NT; nt++) {
            int n = wn * (NT * 8) + nt * 8 + rowin;
            int k = k8 * 8 + bsub * 4;
            uint32_t r0, r1;
            ldsm_x2(r0, r1, wb + (uint32_t)((n * 8 + ((k >> 2) ^ (n & 7))) * 16));
            b0[nt] = cvt_tf32(__uint_as_float(r0));
            b1[nt] = cvt_tf32(__uint_as_float(r1));
        }
        // A fragments + MMAs
#pragma unroll
        for (int mt = 0; mt < 4; mt++) {
            int row = (wm * 4 + mt) * 16 + rhalf * 8 + rowin;
            int col = cb + k8 * 8 + chalf * 4;
            uint32_t aaddr;
            if (XBSRC) aaddr = abase + (uint32_t)(row * 256 + (((col >> 2) ^ (row & 7)) << 4));
            else       aaddr = abase + (uint32_t)(row * (ACT_S * 4) + col * 4);
            uint32_t a[4];
            ldsm_x4(a, aaddr);
#pragma unroll
            for (int nt = 0; nt < NT; nt++)
                mma_tf32(acc[mt][nt], a[0], a[1], a[2], a[3], b0[nt], b1[nt]);
        }
    }
}

template <int NT>
__device__ __forceinline__ void zero_acc(float acc[4][8][4]) {
#pragma unroll
    for (int m = 0; m < 4; m++)
#pragma unroll
        for (int n = 0; n < NT; n++)
#pragma unroll
            for (int q = 0; q < 4; q++) acc[m][n][q] = 0.0f;
}

// Epilogue: bias + (relu) + tf32-round, write to ACT.
template <int NT>
__device__ __forceinline__ void epilogue(float acc[4][8][4], float* __restrict__ ACT,
                                         const float* __restrict__ bb, bool relu,
                                         int lane, int wm, int wn) {
#pragma unroll
    for (int mt = 0; mt < 4; mt++) {
        int row0 = (wm * 4 + mt) * 16 + (lane >> 2);
#pragma unroll
        for (int nt = 0; nt < NT; nt++) {
            int col0 = wn * (NT * 8) + nt * 8 + 2 * (lane & 3);
            float2 bv = __ldg((const float2*)(bb + col0));
            float v0 = acc[mt][nt][0] + bv.x;
            float v1 = acc[mt][nt][1] + bv.y;
            float v2 = acc[mt][nt][2] + bv.x;
            float v3 = acc[mt][nt][3] + bv.y;
            if (relu) {
                v0 = fmaxf(v0, 0.0f); v1 = fmaxf(v1, 0.0f);
                v2 = fmaxf(v2, 0.0f); v3 = fmaxf(v3, 0.0f);
            }
            *(float2*)(ACT + (size_t)row0 * ACT_S + col0) =
                make_float2(rnd_tf32(v0), rnd_tf32(v1));
            *(float2*)(ACT + (size_t)(row0 + 8) * ACT_S + col0) =
                make_float2(rnd_tf32(v2), rnd_tf32(v3));
        }
    }
}

// ----------------------------------------------------------------------------
// Kernel
// ----------------------------------------------------------------------------
__global__ void __launch_bounds__(NTHREADS, 1)
nerf_fused_kernel(Params P, float* __restrict__ out, int ntiles, int Btot) {
    extern __shared__ __align__(16) float smf[];
    float* ACT = smf;                                  // [128][260]
    float* XB  = (float*)((char*)smf + XB_OFF);        // [128][64] swizzled
    const uint32_t sb = smem_u32_of(smf);
    const uint32_t act_u = sb;
    const uint32_t xb_u  = sb + XB_OFF;
    const uint32_t wb0   = sb + WB_OFF;

    const int tid = threadIdx.x;
    const int w = tid >> 5;
    const int lane = tid & 31;
    const int wm = w >> 2;     // 0..1 (M half)
    const int wn = w & 3;      // 0..3 (N quarter)

    const float* __restrict__ xin  = P.p[0];
    const float* __restrict__ ddir = P.p[1];
    const float* __restrict__ wsig = P.p[18];
    const float  bsig = __ldg(P.p[19]);
    const float* __restrict__ wrgb = P.p[30];
    const float* __restrict__ brgb = P.p[31];

    float acc[4][8][4];

    for (int tile = blockIdx.x; tile < ntiles; tile += gridDim.x) {
        __syncthreads();

        // issue weight chunk 0 (layer 0) immediately, then load x
        issue_chunk(P.p[c_widx[0]], c_kact[0], 0, 256, wb0, tid);
        int gi = 1;               // chunks issued
        int ni_li = 0, ni_c = 1;  // next chunk to issue

        // x -> XB cols 0..62 (tf32-rounded, swizzled), col 63 = 0
        {
            const float* xs = xin + (size_t)tile * MTILE * 63;
#pragma unroll 4
            for (int i = 0; i < 32; i++) {
                int e = i * NTHREADS + tid;
                if (e < MTILE * 63) {
                    int r = e / 63, c = e - r * 63;
                    XB[xb_idx(r, c)] = rnd_tf32(__ldg(xs + e));
                }
            }
            if (tid < MTILE) XB[xb_idx(tid, 63)] = 0.0f;
        }

        int g = 0;
        for (int li = 0; li < 13; li++) {
            const int nch = c_nch[li];
            const int N = (li < 9) ? 256 : 128;
            const float* __restrict__ bb = P.p[c_widx[li] + 1];

            if (N == 256) zero_acc<8>(acc); else zero_acc<4>(acc);

            for (int c = 0; c < nch; c++) {
                if (gi < TOT_CHUNKS) {
                    int nli = ni_li, nc = ni_c;
                    issue_chunk(P.p[c_widx[nli]], c_kact[nli], nc * 32,
                                (nli < 9) ? 256 : 128, wb0 + (gi & 1) * WB_BYTES, tid);
                    gi++;
                    if (nc + 1 < c_nch[nli]) ni_c = nc + 1; else { ni_li = nli + 1; ni_c = 0; }
                    cp_wait<1>();
                } else {
                    cp_wait<0>();
                }
                __syncthreads();

                uint32_t wb = wb0 + (uint32_t)(g & 1) * WB_BYTES;
                if (li == 0)
                    compute_chunk<8, true >(acc, xb_u, c * 32, wb, lane, wm, wn);
                else if (li == 5 && c >= 8)
                    compute_chunk<8, true >(acc, xb_u, (c - 8) * 32, wb, lane, wm, wn);
                else if (li == 9 && c == 8)
                    compute_chunk<4, true >(acc, xb_u, 0, wb, lane, wm, wn);
                else if (li < 9)
                    compute_chunk<8, false>(acc, act_u, c * 32, wb, lane, wm, wn);
                else
                    compute_chunk<4, false>(acc, act_u, c * 32, wb, lane, wm, wn);
                __syncthreads();
                g++;
            }

            if (N == 256) epilogue<8>(acc, ACT, bb, li != 8, lane, wm, wn);
            else          epilogue<4>(acc, ACT, bb, li != 8, lane, wm, wn);
            __syncthreads();

            if (li == 7) {
                // sigma = softplus(h7 . wsig + bsig): 2 threads per row
                int r = tid >> 1, half = tid & 1;
                const float* hp = ACT + (size_t)r * ACT_S + half * 128;
                const float* wp = wsig + half * 128;
                float a = 0.0f;
#pragma unroll
                for (int i = 0; i < 32; i++) {
                    float4 h = *(const float4*)(hp + i * 4);
                    float4 wv = __ldg((const float4*)(wp + i * 4));
                    a += h.x * wv.x + h.y * wv.y + h.z * wv.z + h.w * wv.w;
                }
                a += __shfl_xor_sync(0xFFFFFFFFu, a, 1);
                if (!half) {
                    float z = a + bsig;
                    float sp = fmaxf(z, 0.0f) + log1pf(expf(-fabsf(z)));
                    out[(size_t)3 * Btot + (size_t)tile * MTILE + r] = sp;
                }
            }
            if (li == 5) {
                // d -> XB cols 0..26 (x is dead), zero 27..31
                const float* ds = ddir + (size_t)tile * MTILE * 27;
#pragma unroll 4
                for (int i = 0; i < 14; i++) {
                    int e = i * NTHREADS + tid;
                    if (e < MTILE * 27) {
                        int r = e / 27, c2 = e - r * 27;
                        XB[xb_idx(r, c2)] = rnd_tf32(__ldg(ds + e));
                    }
                }
                if (tid < MTILE) {
#pragma unroll
                    for (int c2 = 27; c2 < 32; c2++) XB[xb_idx(tid, c2)] = 0.0f;
                }
                __syncthreads();
            }
            if (li == 12) {
                // rgb = sigmoid(h12 @ Wrgb^T + brgb)
                if (tid < MTILE) {
                    const float* hp = ACT + (size_t)tid * ACT_S;
                    float a0 = 0.0f, a1 = 0.0f, a2 = 0.0f;
#pragma unroll
                    for (int i = 0; i < 32; i++) {
                        float4 h = *(const float4*)(hp + i * 4);
                        float4 w0 = __ldg((const float4*)(wrgb +   0 + i * 4));
                        float4 w1 = __ldg((const float4*)(wrgb + 128 + i * 4));
                        float4 w2 = __ldg((const float4*)(wrgb + 256 + i * 4));
                        a0 += h.x * w0.x + h.y * w0.y + h.z * w0.z + h.w * w0.w;
                        a1 += h.x * w1.x + h.y * w1.y + h.z * w1.z + h.w * w1.w;
                        a2 += h.x * w2.x + h.y * w2.y + h.z * w2.z + h.w * w2.w;
                    }
                    a0 = 1.0f / (1.0f + expf(-(a0 + __ldg(brgb + 0))));
                    a1 = 1.0f / (1.0f + expf(-(a1 + __ldg(brgb + 1))));
                    a2 = 1.0f / (1.0f + expf(-(a2 + __ldg(brgb + 2))));
                    float* orow = out + ((size_t)tile * MTILE + tid) * 3;
                    orow[0] = a0; orow[1] = a1; orow[2] = a2;
                }
            }
        }
    }
}

// ----------------------------------------------------------------------------
extern "C" void kernel_launch(void* const* d_in, const int* in_sizes, int n_in,
                              void* d_out, int out_size) {
    Params P;
    for (int i = 0; i < 32; i++) P.p[i] = (const float*)d_in[i];

    const int B = in_sizes[0] / 63;     // x is [B, 63]
    const int ntiles = B / MTILE;

    cudaFuncSetAttribute(nerf_fused_kernel,
                         cudaFuncAttributeMaxDynamicSharedMemorySize, SMEM_TOTAL);

    int nsm = 148;
    cudaDeviceGetAttribute(&nsm, cudaDevAttrMultiProcessorCount, 0);
    int grid = (nsm < ntiles) ? nsm : ntiles;

    nerf_fused_kernel<<<grid, NTHREADS, SMEM_TOTAL>>>(P, (float*)d_out, ntiles, B);
}

// round 7
// speedup vs baseline: 2.2166x; 2.2166x over previous
#include <cuda_runtime.h>
#include <cuda_fp16.h>
#include <cstdint>
#include <math.h>

// ============================================================================
// Fused NeRF MLP (RadianceField), base sm_100 target (no tcgen05).
// fp16 mma.sync.m16n8k16 (fp32 accum) + ldmatrix, persistent 256-thread CTAs,
// weights pre-converted to fp16 (prepass kernel) and streamed via 4-deep
// cp.async ring, fp16 activations in SMEM.
// ============================================================================

#define NTHREADS 256
#define MTILE    128

// SMEM map (bytes)
#define ACT_OFF  0                     // 128 rows x 512B (256 half cols), swizzled
#define XB_OFF   65536                 // 128 rows x 128B (64 half cols), swizzled
#define WB_OFF   81920                 // 4 x 32768 weight chunk ring
#define WB_BYTES 32768                 // 256 rows x 64 half
#define SMEM_TOTAL (WB_OFF + 4 * WB_BYTES)   // 212992 <= 232448 cap

#define TOT_CHUNKS 45
#define WH_TOTAL   647168

struct Params { const float* p[32]; };

__constant__ int c_widx[13] = {2, 4, 6, 8, 10, 12, 14, 16, 20, 22, 24, 26, 28};
__constant__ int c_kact[13] = {63, 256, 256, 256, 256, 319, 256, 256, 256, 283, 128, 128, 128};
__constant__ int c_nch [13] = { 1,   4,   4,   4,   4,   5,   4,   4,   4,   5,   2,   2,   2};
__constant__ int c_woff[13] = {0, 16384, 81920, 147456, 212992, 278528, 360448,
                               425984, 491520, 557056, 598016, 614400, 630784};

// fp16 weights, chunk-major: (li, chunk, n, kin) -> woff + chunk*N*64 + n*64 + kin
__device__ __align__(16) __half g_wh[WH_TOTAL];

// ----------------------------------------------------------------------------
__device__ __forceinline__ uint32_t smem_u32_of(const void* p) {
    uint32_t a;
    asm("{ .reg .u64 t; cvta.to.shared.u64 t, %1; cvt.u32.u64 %0, t; }" : "=r"(a) : "l"(p));
    return a;
}
__device__ __forceinline__ void cp_async16(uint32_t dst, const void* src) {
    asm volatile("cp.async.ca.shared.global [%0], [%1], 16;" :: "r"(dst), "l"(src));
}
__device__ __forceinline__ void cp_commit() { asm volatile("cp.async.commit_group;"); }
template <int N> __device__ __forceinline__ void cp_wait() {
    asm volatile("cp.async.wait_group %0;" :: "n"(N));
}
__device__ __forceinline__ void ldsm_x4(uint32_t r[4], uint32_t addr) {
    asm volatile("ldmatrix.sync.aligned.m8n8.x4.shared.b16 {%0,%1,%2,%3}, [%4];"
                 : "=r"(r[0]), "=r"(r[1]), "=r"(r[2]), "=r"(r[3]) : "r"(addr));
}
__device__ __forceinline__ void ldsm_x2(uint32_t& r0, uint32_t& r1, uint32_t addr) {
    asm volatile("ldmatrix.sync.aligned.m8n8.x2.shared.b16 {%0,%1}, [%2];"
                 : "=r"(r0), "=r"(r1) : "r"(addr));
}
__device__ __forceinline__ void mma_f16(float c[4], uint32_t a0, uint32_t a1,
                                        uint32_t a2, uint32_t a3,
                                        uint32_t b0, uint32_t b1) {
    asm volatile(
        "mma.sync.aligned.m16n8k16.row.col.f32.f16.f16.f32 "
        "{%0,%1,%2,%3}, {%4,%5,%6,%7}, {%8,%9}, {%0,%1,%2,%3};"
        : "+f"(c[0]), "+f"(c[1]), "+f"(c[2]), "+f"(c[3])
        : "r"(a0), "r"(a1), "r"(a2), "r"(a3), "r"(b0), "r"(b1));
}
__device__ __forceinline__ void sts32(uint32_t addr, uint32_t v) {
    asm volatile("st.shared.b32 [%0], %1;" :: "r"(addr), "r"(v));
}
__device__ __forceinline__ void sts128(uint32_t addr, uint32_t a, uint32_t b,
                                       uint32_t c, uint32_t d) {
    asm volatile("st.shared.v4.b32 [%0], {%1,%2,%3,%4};"
                 :: "r"(addr), "r"(a), "r"(b), "r"(c), "r"(d));
}
__device__ __forceinline__ uint4 lds128(uint32_t addr) {
    uint4 u;
    asm volatile("ld.shared.v4.b32 {%0,%1,%2,%3}, [%4];"
                 : "=r"(u.x), "=r"(u.y), "=r"(u.z), "=r"(u.w) : "r"(addr));
    return u;
}
__device__ __forceinline__ uint32_t h2u(__half2 h) { return *(uint32_t*)&h; }

// ============================================================================
// Prepass: fp32 weights -> fp16, zero-padded, chunk-major layout.
// ============================================================================
__global__ void wconv_kernel(Params P) {
    int i = blockIdx.x * blockDim.x + threadIdx.x;
    if (i >= WH_TOTAL) return;
    int li = 0;
#pragma unroll
    for (int l = 1; l < 13; l++) if (i >= c_woff[l]) li = l;
    int e = i - c_woff[li];
    int N = (li < 9) ? 256 : 128;
    int cN = N * 64;
    int c = e / cN;
    int r = e - c * cN;
    int n = r >> 6;
    int k = c * 64 + (r & 63);
    int Kact = c_kact[li];
    float v = (k < Kact) ? __ldg(P.p[c_widx[li]] + (size_t)n * Kact + k) : 0.0f;
    g_wh[i] = __float2half_rn(v);
}

// ============================================================================
// Main kernel helpers
// ============================================================================
// issue one 64-k chunk of fp16 weights: N rows x 128B, XOR-swizzled 16B granules
__device__ __forceinline__ void issue_whalf(const __half* __restrict__ Wc, int N,
                                            uint32_t wbbase, int tid) {
    const int iters = N >> 5;   // N*8 granules / 256 threads
#pragma unroll 8
    for (int i = 0; i < iters; i++) {
        int f = i * NTHREADS + tid;
        int n = f >> 3, gr = f & 7;
        cp_async16(wbbase + (uint32_t)((n * 8 + (gr ^ (n & 7))) * 16), Wc + f * 8);
    }
    cp_commit();
}

// compute one 64-k chunk; NT=8 (N=256) or 4 (N=128); XBSRC: A from XB (cb==0)
template <int NT, bool XBSRC>
__device__ __forceinline__ void compute_chunk(float acc[4][8][4], uint32_t abase, int cb,
                                              uint32_t wb, int lane, int wm, int wn) {
    const int arow = lane & 15;
    const int asel = lane >> 4;          // +8 k cols
    const int brow = lane & 7;
    const int bsel = (lane >> 3) & 1;    // +8 k cols (lanes 0..15 supply addrs)
#pragma unroll
    for (int ks = 0; ks < 4; ks++) {
        const int kb = ks * 16;
        uint32_t b0[NT], b1[NT];
#pragma unroll
        for (int nt = 0; nt < NT; nt++) {
            int n = wn * (NT * 8) + nt * 8 + brow;
            int gr = (kb >> 3) + bsel;
            ldsm_x2(b0[nt], b1[nt], wb + (uint32_t)((n * 8 + (gr ^ (n & 7))) * 16));
        }
#pragma unroll
        for (int mt = 0; mt < 4; mt++) {
            int row = wm * 64 + mt * 16 + arow;
            uint32_t a[4];
            if (XBSRC) {
                int gr = (kb >> 3) + asel;       // 0..7
                ldsm_x4(a, abase + (uint32_t)(row * 128 + (gr ^ (row & 7)) * 16));
            } else {
                int gr = ((cb + kb) >> 3) + asel; // 0..31, XOR flips low 3 bits
                ldsm_x4(a, abase + (uint32_t)(row * 512 + (gr ^ (row & 7)) * 16));
            }
#pragma unroll
            for (int nt = 0; nt < NT; nt++)
                mma_f16(acc[mt][nt], a[0], a[1], a[2], a[3], b0[nt], b1[nt]);
        }
    }
}

template <int NT>
__device__ __forceinline__ void zero_acc(float acc[4][8][4]) {
#pragma unroll
    for (int m = 0; m < 4; m++)
#pragma unroll
        for (int n = 0; n < NT; n++)
#pragma unroll
            for (int q = 0; q < 4; q++) acc[m][n][q] = 0.0f;
}

template <int NT>
__device__ __forceinline__ void epilogue(float acc[4][8][4], uint32_t act_u,
                                         const float* __restrict__ bb, bool relu,
                                         int lane, int wm, int wn) {
#pragma unroll
    for (int mt = 0; mt < 4; mt++) {
        int row0 = wm * 64 + mt * 16 + (lane >> 2);
        int row1 = row0 + 8;
#pragma unroll
        for (int nt = 0; nt < NT; nt++) {
            int col0 = wn * (NT * 8) + nt * 8 + 2 * (lane & 3);
            float2 bv = __ldg((const float2*)(bb + col0));
            float v0 = acc[mt][nt][0] + bv.x;
            float v1 = acc[mt][nt][1] + bv.y;
            float v2 = acc[mt][nt][2] + bv.x;
            float v3 = acc[mt][nt][3] + bv.y;
            if (relu) {
                v0 = fmaxf(v0, 0.0f); v1 = fmaxf(v1, 0.0f);
                v2 = fmaxf(v2, 0.0f); v3 = fmaxf(v3, 0.0f);
            }
            int g = col0 >> 3, cb2 = (col0 & 7) * 2;
            sts32(act_u + (uint32_t)(row0 * 512 + (g ^ (row0 & 7)) * 16 + cb2),
                  h2u(__floats2half2_rn(v0, v1)));
            sts32(act_u + (uint32_t)(row1 * 512 + (g ^ (row1 & 7)) * 16 + cb2),
                  h2u(__floats2half2_rn(v2, v3)));
        }
    }
}

// ============================================================================
// Kernel
// ============================================================================
__global__ void __launch_bounds__(NTHREADS, 1)
nerf_fused_fp16(Params P, float* __restrict__ out, int ntiles, int Btot) {
    extern __shared__ __align__(1024) char sm[];
    const uint32_t sb = smem_u32_of(sm);
    const uint32_t act_u = sb + ACT_OFF;
    const uint32_t xb_u  = sb + XB_OFF;
    const uint32_t wb_u  = sb + WB_OFF;

    const int tid = threadIdx.x;
    const int lane = tid & 31;
    const int w = tid >> 5;
    const int wm = w >> 2;
    const int wn = w & 3;

    const float* __restrict__ xin  = P.p[0];
    const float* __restrict__ ddir = P.p[1];
    const float* __restrict__ wsig = P.p[18];
    const float  bsig = __ldg(P.p[19]);
    const float* __restrict__ wrgb = P.p[30];
    const float* __restrict__ brgb = P.p[31];

    float acc[4][8][4];
    uint32_t icnt = 0;   // chunks issued (monotonic -> ring slot)
    uint32_t ccnt = 0;   // chunks computed (monotonic -> ring slot)

    for (int tile = blockIdx.x; tile < ntiles; tile += gridDim.x) {
        __syncthreads();   // prev tile fully done (heads, epilogues)

        // ---- x -> XB (fp16, swizzled); cols 0..62 = x, col 63 = 0
        {
            int r = tid >> 1, sel = tid & 1;
            const float* xr = xin + ((size_t)tile * MTILE + r) * 63;
#pragma unroll
            for (int gi = 0; gi < 4; gi++) {
                int g = sel * 4 + gi;
                int c0 = g * 8;
                uint32_t u[4];
#pragma unroll
                for (int q = 0; q < 4; q++) {
                    int c = c0 + q * 2;
                    float f0 = (c < 63) ? __ldg(xr + c) : 0.0f;
                    float f1 = (c + 1 < 63) ? __ldg(xr + c + 1) : 0.0f;
                    u[q] = h2u(__floats2half2_rn(f0, f1));
                }
                sts128(xb_u + (uint32_t)(r * 128 + (g ^ (r & 7)) * 16),
                       u[0], u[1], u[2], u[3]);
            }
        }

        // ---- prologue: issue tile chunks 0..2
        int ni_li = 0, ni_c = 0;
#pragma unroll
        for (int j = 0; j < 3; j++) {
            int N = (ni_li < 9) ? 256 : 128;
            const __half* wsrc = g_wh + c_woff[ni_li] + (size_t)ni_c * (N * 64);
            issue_whalf(wsrc, N, wb_u + (icnt & 3) * WB_BYTES, tid);
            icnt++;
            if (++ni_c == c_nch[ni_li]) { ni_li++; ni_c = 0; }
        }

        // ---- layer loop
        for (int li = 0; li < 13; li++) {
            const int nch = c_nch[li];
            const bool n256 = (li < 9);
            const float* __restrict__ bb = P.p[c_widx[li] + 1];

            if (n256) zero_acc<8>(acc); else zero_acc<4>(acc);

            for (int c = 0; c < nch; c++) {
                cp_wait<2>();      // this chunk's group done (per-thread)
                __syncthreads();   // all data visible; all warps done w/ c-1

                // lookahead issue (or empty commit to keep group invariant)
                if (ni_li < 13) {
                    int N = (ni_li < 9) ? 256 : 128;
                    const __half* wsrc = g_wh + c_woff[ni_li] + (size_t)ni_c * (N * 64);
                    issue_whalf(wsrc, N, wb_u + (icnt & 3) * WB_BYTES, tid);
                    icnt++;
                    if (++ni_c == c_nch[ni_li]) { ni_li++; ni_c = 0; }
                } else {
                    cp_commit();
                }

                uint32_t wb = wb_u + (ccnt & 3) * WB_BYTES;
                bool xbsrc = (li == 0) || (li == 5 && c == 4) || (li == 9 && c == 4);
                if (n256) {
                    if (xbsrc) compute_chunk<8, true >(acc, xb_u, 0, wb, lane, wm, wn);
                    else       compute_chunk<8, false>(acc, act_u, c * 64, wb, lane, wm, wn);
                } else {
                    if (xbsrc) compute_chunk<4, true >(acc, xb_u, 0, wb, lane, wm, wn);
                    else       compute_chunk<4, false>(acc, act_u, c * 64, wb, lane, wm, wn);
                }
                ccnt++;
            }

            __syncthreads();   // all chunk reads of ACT done -> safe to overwrite
            if (n256) epilogue<8>(acc, act_u, bb, li != 8, lane, wm, wn);
            else      epilogue<4>(acc, act_u, bb, li != 8, lane, wm, wn);

            if (li == 5) {
                // d -> XB (x is dead): cols 0..26 = d, 27..63 = 0
                int r = tid >> 1, sel = tid & 1;
                const float* dr = ddir + ((size_t)tile * MTILE + r) * 27;
#pragma unroll
                for (int gi = 0; gi < 4; gi++) {
                    int g = sel * 4 + gi;
                    int c0 = g * 8;
                    uint32_t u[4];
#pragma unroll
                    for (int q = 0; q < 4; q++) {
                        int c = c0 + q * 2;
                        float f0 = (c < 27) ? __ldg(dr + c) : 0.0f;
                        float f1 = (c + 1 < 27) ? __ldg(dr + c + 1) : 0.0f;
                        u[q] = h2u(__floats2half2_rn(f0, f1));
                    }
                    sts128(xb_u + (uint32_t)(r * 128 + (g ^ (r & 7)) * 16),
                           u[0], u[1], u[2], u[3]);
                }
            }
            __syncthreads();   // epilogue (and d) visible

            if (li == 7) {
                // sigma = softplus(h7 . wsig + bsig); 2 threads/row
                int r = tid >> 1, sel = tid & 1;
                float a = 0.0f;
#pragma unroll
                for (int i = 0; i < 16; i++) {
                    int g = sel * 16 + i;
                    uint4 u = lds128(act_u + (uint32_t)(r * 512 + (g ^ (r & 7)) * 16));
                    __half2* hp = (__half2*)&u;
                    float4 w0 = __ldg((const float4*)(wsig + sel * 128 + i * 8));
                    float4 w1 = __ldg((const float4*)(wsig + sel * 128 + i * 8 + 4));
                    float2 f;
                    f = __half22float2(hp[0]); a += f.x * w0.x + f.y * w0.y;
                    f = __half22float2(hp[1]); a += f.x * w0.z + f.y * w0.w;
                    f = __half22float2(hp[2]); a += f.x * w1.x + f.y * w1.y;
                    f = __half22float2(hp[3]); a += f.x * w1.z + f.y * w1.w;
                }
                a += __shfl_xor_sync(0xFFFFFFFFu, a, 1);
                if (!sel) {
                    float z = a + bsig;
                    float sp = fmaxf(z, 0.0f) + log1pf(expf(-fabsf(z)));
                    out[(size_t)3 * Btot + (size_t)tile * MTILE + r] = sp;
                }
            }
            if (li == 12 && tid < MTILE) {
                // rgb = sigmoid(h12 @ Wrgb^T + brgb)
                int r = tid;
                float a0 = 0.0f, a1 = 0.0f, a2 = 0.0f;
#pragma unroll
                for (int i = 0; i < 16; i++) {
                    uint4 u = lds128(act_u + (uint32_t)(r * 512 + (i ^ (r & 7)) * 16));
                    __half2* hp = (__half2*)&u;
                    float4 wa0 = __ldg((const float4*)(wrgb + i * 8));
                    float4 wa1 = __ldg((const float4*)(wrgb + i * 8 + 4));
                    float4 wb0 = __ldg((const float4*)(wrgb + 128 + i * 8));
                    float4 wb1 = __ldg((const float4*)(wrgb + 128 + i * 8 + 4));
                    float4 wc0 = __ldg((const float4*)(wrgb + 256 + i * 8));
                    float4 wc1 = __ldg((const float4*)(wrgb + 256 + i * 8 + 4));
                    float2 f0 = __half22float2(hp[0]);
                    float2 f1 = __half22float2(hp[1]);
                    float2 f2 = __half22float2(hp[2]);
                    float2 f3 = __half22float2(hp[3]);
                    a0 += f0.x*wa0.x + f0.y*wa0.y + f1.x*wa0.z + f1.y*wa0.w
                        + f2.x*wa1.x + f2.y*wa1.y + f3.x*wa1.z + f3.y*wa1.w;
                    a1 += f0.x*wb0.x + f0.y*wb0.y + f1.x*wb0.z + f1.y*wb0.w
                        + f2.x*wb1.x + f2.y*wb1.y + f3.x*wb1.z + f3.y*wb1.w;
                    a2 += f0.x*wc0.x + f0.y*wc0.y + f1.x*wc0.z + f1.y*wc0.w
                        + f2.x*wc1.x + f2.y*wc1.y + f3.x*wc1.z + f3.y*wc1.w;
                }
                a0 = 1.0f / (1.0f + expf(-(a0 + __ldg(brgb + 0))));
                a1 = 1.0f / (1.0f + expf(-(a1 + __ldg(brgb + 1))));
                a2 = 1.0f / (1.0f + expf(-(a2 + __ldg(brgb + 2))));
                float* orow = out + ((size_t)tile * MTILE + r) * 3;
                orow[0] = a0; orow[1] = a1; orow[2] = a2;
            }
        }
    }
}

// ----------------------------------------------------------------------------
extern "C" void kernel_launch(void* const* d_in, const int* in_sizes, int n_in,
                              void* d_out, int out_size) {
    Params P;
    for (int i = 0; i < 32; i++) P.p[i] = (const float*)d_in[i];

    const int B = in_sizes[0] / 63;     // x is [B, 63]
    const int ntiles = B / MTILE;

    // prepass: weights -> fp16 chunk-major layout
    wconv_kernel<<<(WH_TOTAL + 255) / 256, 256>>>(P);

    cudaFuncSetAttribute(nerf_fused_fp16,
                         cudaFuncAttributeMaxDynamicSharedMemorySize, SMEM_TOTAL);

    int nsm = 148;
    cudaDeviceGetAttribute(&nsm, cudaDevAttrMultiProcessorCount, 0);
    int grid = (nsm < ntiles) ? nsm : ntiles;

    nerf_fused_fp16<<<grid, NTHREADS, SMEM_TOTAL>>>(P, (float*)d_out, ntiles, B);
}

// round 8
// speedup vs baseline: 2.3224x; 1.0477x over previous
#include <cuda_runtime.h>
#include <cuda_fp16.h>
#include <cstdint>
#include <math.h>

// ============================================================================
// Fused NeRF MLP (RadianceField), base sm_100 target (no tcgen05).
// fp16 mma.sync.m16n8k16 (fp32 accum) + ldmatrix.x4, persistent 256-thread
// CTAs, weights pre-converted to fp16 and streamed in 128-k chunks through a
// 2-slot cp.async ring (lookahead 1), fp16 activations in SMEM.
// ============================================================================

#define NTHREADS 256
#define MTILE    128

// SMEM map (bytes)
#define ACT_OFF  0                     // 128 rows x 512B (256 half cols), swizzled
#define XB_OFF   65536                 // 128 rows x 256B (128 half cols), swizzled
#define WB_OFF   98304                 // 2 x 65536 weight chunk ring
#define WB_BYTES 65536                 // slot: 256 rows x 256B
#define SMEM_TOTAL (WB_OFF + 2 * WB_BYTES)   // 229376 <= 232448 cap

#define NCHUNKS  24
#define WH_TOTAL 647168

struct Params { const float* p[32]; };

__constant__ int c_widx[13] = {2, 4, 6, 8, 10, 12, 14, 16, 20, 22, 24, 26, 28};
__constant__ int c_kact[13] = {63, 256, 256, 256, 256, 319, 256, 256, 256, 283, 128, 128, 128};
__constant__ int c_kpad[13] = {64, 256, 256, 256, 256, 320, 256, 256, 256, 320, 128, 128, 128};
__constant__ int c_nch [13] = { 1,   2,   2,   2,   2,   3,   2,   2,   2,   3,   1,   1,   1};
__constant__ int c_woff[13] = {0, 16384, 81920, 147456, 212992, 278528, 360448,
                               425984, 491520, 557056, 598016, 614400, 630784};
// flat chunk tables
__constant__ int ck_li[NCHUNKS] = {0, 1,1, 2,2, 3,3, 4,4, 5,5,5, 6,6, 7,7, 8,8, 9,9,9, 10, 11, 12};
__constant__ int ck_c [NCHUNKS] = {0, 0,1, 0,1, 0,1, 0,1, 0,1,2, 0,1, 0,1, 0,1, 0,1,2, 0, 0, 0};

// fp16 weights, per-layer row-major [n][Kpad] (zero-padded)
__device__ __align__(16) __half g_wh[WH_TOTAL];

// ----------------------------------------------------------------------------
__device__ __forceinline__ uint32_t smem_u32_of(const void* p) {
    uint32_t a;
    asm("{ .reg .u64 t; cvta.to.shared.u64 t, %1; cvt.u32.u64 %0, t; }" : "=r"(a) : "l"(p));
    return a;
}
__device__ __forceinline__ void cp_async16(uint32_t dst, const void* src) {
    asm volatile("cp.async.cg.shared.global [%0], [%1], 16;" :: "r"(dst), "l"(src));
}
__device__ __forceinline__ void cp_commit() { asm volatile("cp.async.commit_group;"); }
template <int N> __device__ __forceinline__ void cp_wait() {
    asm volatile("cp.async.wait_group %0;" :: "n"(N));
}
__device__ __forceinline__ void ldsm_x4(uint32_t r[4], uint32_t addr) {
    asm volatile("ldmatrix.sync.aligned.m8n8.x4.shared.b16 {%0,%1,%2,%3}, [%4];"
                 : "=r"(r[0]), "=r"(r[1]), "=r"(r[2]), "=r"(r[3]) : "r"(addr));
}
__device__ __forceinline__ void mma_f16(float c[4], uint32_t a0, uint32_t a1,
                                        uint32_t a2, uint32_t a3,
                                        uint32_t b0, uint32_t b1) {
    asm volatile(
        "mma.sync.aligned.m16n8k16.row.col.f32.f16.f16.f32 "
        "{%0,%1,%2,%3}, {%4,%5,%6,%7}, {%8,%9}, {%0,%1,%2,%3};"
        : "+f"(c[0]), "+f"(c[1]), "+f"(c[2]), "+f"(c[3])
        : "r"(a0), "r"(a1), "r"(a2), "r"(a3), "r"(b0), "r"(b1));
}
__device__ __forceinline__ void sts32(uint32_t addr, uint32_t v) {
    asm volatile("st.shared.b32 [%0], %1;" :: "r"(addr), "r"(v));
}
__device__ __forceinline__ void sts128(uint32_t addr, uint32_t a, uint32_t b,
                                       uint32_t c, uint32_t d) {
    asm volatile("st.shared.v4.b32 [%0], {%1,%2,%3,%4};"
                 :: "r"(addr), "r"(a), "r"(b), "r"(c), "r"(d));
}
__device__ __forceinline__ uint4 lds128(uint32_t addr) {
    uint4 u;
    asm volatile("ld.shared.v4.b32 {%0,%1,%2,%3}, [%4];"
                 : "=r"(u.x), "=r"(u.y), "=r"(u.z), "=r"(u.w) : "r"(addr));
    return u;
}
__device__ __forceinline__ uint32_t h2u(__half2 h) { return *(uint32_t*)&h; }

// ============================================================================
// Prepass: fp32 weights -> fp16, zero-padded, per-layer [n][Kpad] row-major
// ============================================================================
__global__ void wconv_kernel(Params P) {
    int i = blockIdx.x * blockDim.x + threadIdx.x;
    if (i >= WH_TOTAL) return;
    int li = 0;
#pragma unroll
    for (int l = 1; l < 13; l++) if (i >= c_woff[l]) li = l;
    int e = i - c_woff[li];
    int Kp = c_kpad[li];
    int n = e / Kp;
    int k = e - n * Kp;
    int Kact = c_kact[li];
    float v = (k < Kact) ? __ldg(P.p[c_widx[li]] + (size_t)n * Kact + k) : 0.0f;
    g_wh[i] = __float2half_rn(v);
}

// ============================================================================
// Weight chunk issue: slice [kk, kk+KS*16) of layer li into ring slot.
// Slot layout: row n = 256B, 16B granules XOR-swizzled by (n&7).
// ============================================================================
__device__ __forceinline__ void issue_chunk(int idx, uint32_t slot, int tid) {
    const int li = ck_li[idx], c = ck_c[idx];
    const int N = (li < 9) ? 256 : 128;
    const int Kp = c_kpad[li];
    const int KS = (li == 0 || ((li == 5 || li == 9) && c == 2)) ? 4 : 8;
    const int ks2 = 2 * KS;                 // granules per row
    const __half* __restrict__ base = g_wh + c_woff[li] + c * 128;
    const int tot = N * ks2;
    const int sh = (KS == 8) ? 4 : 3;
    const int msk = ks2 - 1;
    for (int f = tid; f < tot; f += NTHREADS) {
        int n = f >> sh, g = f & msk;
        cp_async16(slot + (uint32_t)(n * 256 + ((g ^ (n & 7)) << 4)),
                   base + (size_t)n * Kp + g * 8);
    }
    cp_commit();
}

// ============================================================================
// Compute one chunk: KS k-steps of 16. Warp (wm, wn): rows [wm*64,+64),
// cols [wn*NT*8, +NT*8). XBSRC: A from XB (256B rows), else ACT (512B rows).
// ============================================================================
template <int NT, int KS, bool XBSRC>
__device__ __forceinline__ void compute_chunk(float acc[4][8][4], uint32_t abase, int cb,
                                              uint32_t wb, int lane, int wm, int wn) {
    const int arow = lane & 15;
    const int asel = lane >> 4;
    const int brow = lane & 7;
    const int bsel = (lane >> 3) & 1;
    const int bnto = lane >> 4;
    const int RS = XBSRC ? 256 : 512;
    const uint32_t a_base = abase + (uint32_t)((wm * 64 + arow) * RS);
    const int sA = arow & 7;
    const int cbb = (cb >> 3) + asel;
#pragma unroll
    for (int ks = 0; ks < KS; ks++) {
        uint32_t b0[NT], b1[NT];
#pragma unroll
        for (int p = 0; p < NT / 2; p++) {
            int n = wn * (NT * 8) + (2 * p + bnto) * 8 + brow;
            int gr = ks * 2 + bsel;
            uint32_t q[4];
            ldsm_x4(q, wb + (uint32_t)(n * 256 + ((gr ^ brow) << 4)));
            b0[2 * p] = q[0]; b1[2 * p] = q[1];
            b0[2 * p + 1] = q[2]; b1[2 * p + 1] = q[3];
        }
#pragma unroll
        for (int mt = 0; mt < 4; mt++) {
            uint32_t a[4];
            int gr = cbb + ks * 2;
            ldsm_x4(a, a_base + (uint32_t)(mt * 16 * RS + ((gr ^ sA) << 4)));
#pragma unroll
            for (int nt = 0; nt < NT; nt++)
                mma_f16(acc[mt][nt], a[0], a[1], a[2], a[3], b0[nt], b1[nt]);
        }
    }
}

template <int NT>
__device__ __forceinline__ void zero_acc(float acc[4][8][4]) {
#pragma unroll
    for (int m = 0; m < 4; m++)
#pragma unroll
        for (int n = 0; n < NT; n++)
#pragma unroll
            for (int q = 0; q < 4; q++) acc[m][n][q] = 0.0f;
}

template <int NT>
__device__ __forceinline__ void epilogue(float acc[4][8][4], uint32_t act_u,
                                         const float* __restrict__ bb, bool relu,
                                         int lane, int wm, int wn) {
#pragma unroll
    for (int mt = 0; mt < 4; mt++) {
        int row0 = wm * 64 + mt * 16 + (lane >> 2);
        int row1 = row0 + 8;
#pragma unroll
        for (int nt = 0; nt < NT; nt++) {
            int col0 = wn * (NT * 8) + nt * 8 + 2 * (lane & 3);
            float2 bv = __ldg((const float2*)(bb + col0));
            float v0 = acc[mt][nt][0] + bv.x;
            float v1 = acc[mt][nt][1] + bv.y;
            float v2 = acc[mt][nt][2] + bv.x;
            float v3 = acc[mt][nt][3] + bv.y;
            if (relu) {
                v0 = fmaxf(v0, 0.0f); v1 = fmaxf(v1, 0.0f);
                v2 = fmaxf(v2, 0.0f); v3 = fmaxf(v3, 0.0f);
            }
            int g = col0 >> 3, cb2 = (col0 & 7) * 2;
            sts32(act_u + (uint32_t)(row0 * 512 + ((g ^ (row0 & 7)) << 4) + cb2),
                  h2u(__floats2half2_rn(v0, v1)));
            sts32(act_u + (uint32_t)(row1 * 512 + ((g ^ (row1 & 7)) << 4) + cb2),
                  h2u(__floats2half2_rn(v2, v3)));
        }
    }
}

// ============================================================================
// Kernel
// ============================================================================
__global__ void __launch_bounds__(NTHREADS, 1)
nerf_fused_fp16(Params P, float* __restrict__ out, int ntiles, int Btot) {
    extern __shared__ __align__(1024) char sm[];
    const uint32_t sb = smem_u32_of(sm);
    const uint32_t act_u = sb + ACT_OFF;
    const uint32_t xb_u  = sb + XB_OFF;
    const uint32_t wb_u  = sb + WB_OFF;

    const int tid = threadIdx.x;
    const int lane = tid & 31;
    const int w = tid >> 5;
    const int wm = w >> 2;
    const int wn = w & 3;

    const float* __restrict__ xin  = P.p[0];
    const float* __restrict__ ddir = P.p[1];
    const float* __restrict__ wsig = P.p[18];
    const float  bsig = __ldg(P.p[19]);
    const float* __restrict__ wrgb = P.p[30];
    const float* __restrict__ brgb = P.p[31];

    float acc[4][8][4];

    for (int tile = blockIdx.x; tile < ntiles; tile += gridDim.x) {
        __syncthreads();   // prev tile fully done

        // ---- prologue: issue chunk 0 into slot 0
        issue_chunk(0, wb_u, tid);

        // ---- x -> XB (fp16, swizzled); cols 0..62 = x, 63..127 = 0
        {
            int r = tid >> 1, sel = tid & 1;
            const float* xr = xin + ((size_t)tile * MTILE + r) * 63;
#pragma unroll
            for (int gi = 0; gi < 8; gi++) {
                int g = sel * 8 + gi;
                int c0 = g * 8;
                uint32_t u[4];
#pragma unroll
                for (int q = 0; q < 4; q++) {
                    int c = c0 + q * 2;
                    float f0 = (c < 63) ? __ldg(xr + c) : 0.0f;
                    float f1 = (c + 1 < 63) ? __ldg(xr + c + 1) : 0.0f;
                    u[q] = h2u(__floats2half2_rn(f0, f1));
                }
                sts128(xb_u + (uint32_t)(r * 256 + ((g ^ (r & 7)) << 4)),
                       u[0], u[1], u[2], u[3]);
            }
        }

        int gc = 0;
        for (int li = 0; li < 13; li++) {
            const int nch = c_nch[li];
            const bool n256 = (li < 9);
            const float* __restrict__ bb = P.p[c_widx[li] + 1];

            if (n256) zero_acc<8>(acc); else zero_acc<4>(acc);

            for (int c = 0; c < nch; c++) {
                cp_wait<0>();      // this chunk's data arrived (per-thread)
                __syncthreads();   // visible to all; all warps done w/ gc-1

                if (gc + 1 < NCHUNKS)
                    issue_chunk(gc + 1, wb_u + ((gc + 1) & 1) * WB_BYTES, tid);

                const uint32_t wb = wb_u + (gc & 1) * WB_BYTES;
                if (li == 0)
                    compute_chunk<8, 4, true >(acc, xb_u, 0, wb, lane, wm, wn);
                else if (li == 5 && c == 2)
                    compute_chunk<8, 4, true >(acc, xb_u, 0, wb, lane, wm, wn);
                else if (li == 9 && c == 2)
                    compute_chunk<4, 4, true >(acc, xb_u, 0, wb, lane, wm, wn);
                else if (n256)
                    compute_chunk<8, 8, false>(acc, act_u, c * 128, wb, lane, wm, wn);
                else
                    compute_chunk<4, 8, false>(acc, act_u, c * 128, wb, lane, wm, wn);
                gc++;
            }

            __syncthreads();   // all reads of ACT/XB for this layer done
            if (n256) epilogue<8>(acc, act_u, bb, li != 8, lane, wm, wn);
            else      epilogue<4>(acc, act_u, bb, li != 8, lane, wm, wn);

            if (li == 5) {
                // d -> XB (x is dead): cols 0..26 = d, rest 0
                int r = tid >> 1, sel = tid & 1;
                const float* dr = ddir + ((size_t)tile * MTILE + r) * 27;
#pragma unroll
                for (int gi = 0; gi < 8; gi++) {
                    int g = sel * 8 + gi;
                    int c0 = g * 8;
                    uint32_t u[4];
#pragma unroll
                    for (int q = 0; q < 4; q++) {
                        int c = c0 + q * 2;
                        float f0 = (c < 27) ? __ldg(dr + c) : 0.0f;
                        float f1 = (c + 1 < 27) ? __ldg(dr + c + 1) : 0.0f;
                        u[q] = h2u(__floats2half2_rn(f0, f1));
                    }
                    sts128(xb_u + (uint32_t)(r * 256 + ((g ^ (r & 7)) << 4)),
                           u[0], u[1], u[2], u[3]);
                }
            }

            if (li == 7) {
                __syncthreads();   // epilogue visible
                // sigma = softplus(h7 . wsig + bsig); 2 threads/row
                int r = tid >> 1, sel = tid & 1;
                float a = 0.0f;
#pragma unroll
                for (int i = 0; i < 16; i++) {
                    int g = sel * 16 + i;
                    uint4 u = lds128(act_u + (uint32_t)(r * 512 + ((g ^ (r & 7)) << 4)));
                    __half2* hp = (__half2*)&u;
                    float4 w0 = __ldg((const float4*)(wsig + sel * 128 + i * 8));
                    float4 w1 = __ldg((const float4*)(wsig + sel * 128 + i * 8 + 4));
                    float2 f;
                    f = __half22float2(hp[0]); a += f.x * w0.x + f.y * w0.y;
                    f = __half22float2(hp[1]); a += f.x * w0.z + f.y * w0.w;
                    f = __half22float2(hp[2]); a += f.x * w1.x + f.y * w1.y;
                    f = __half22float2(hp[3]); a += f.x * w1.z + f.y * w1.w;
                }
                a += __shfl_xor_sync(0xFFFFFFFFu, a, 1);
                if (!sel) {
                    float z = a + bsig;
                    float sp = fmaxf(z, 0.0f) + log1pf(expf(-fabsf(z)));
                    out[(size_t)3 * Btot + (size_t)tile * MTILE + r] = sp;
                }
            }
            if (li == 12) {
                __syncthreads();   // epilogue visible
                if (tid < MTILE) {
                    // rgb = sigmoid(h12 @ Wrgb^T + brgb)
                    int r = tid;
                    float a0 = 0.0f, a1 = 0.0f, a2 = 0.0f;
#pragma unroll
                    for (int i = 0; i < 16; i++) {
                        uint4 u = lds128(act_u + (uint32_t)(r * 512 + ((i ^ (r & 7)) << 4)));
                        __half2* hp = (__half2*)&u;
                        float4 wa0 = __ldg((const float4*)(wrgb + i * 8));
                        float4 wa1 = __ldg((const float4*)(wrgb + i * 8 + 4));
                        float4 wb0 = __ldg((const float4*)(wrgb + 128 + i * 8));
                        float4 wb1 = __ldg((const float4*)(wrgb + 128 + i * 8 + 4));
                        float4 wc0 = __ldg((const float4*)(wrgb + 256 + i * 8));
                        float4 wc1 = __ldg((const float4*)(wrgb + 256 + i * 8 + 4));
                        float2 f0 = __half22float2(hp[0]);
                        float2 f1 = __half22float2(hp[1]);
                        float2 f2 = __half22float2(hp[2]);
                        float2 f3 = __half22float2(hp[3]);
                        a0 += f0.x*wa0.x + f0.y*wa0.y + f1.x*wa0.z + f1.y*wa0.w
                            + f2.x*wa1.x + f2.y*wa1.y + f3.x*wa1.z + f3.y*wa1.w;
                        a1 += f0.x*wb0.x + f0.y*wb0.y + f1.x*wb0.z + f1.y*wb0.w
                            + f2.x*wb1.x + f2.y*wb1.y + f3.x*wb1.z + f3.y*wb1.w;
                        a2 += f0.x*wc0.x + f0.y*wc0.y + f1.x*wc0.z + f1.y*wc0.w
                            + f2.x*wc1.x + f2.y*wc1.y + f3.x*wc1.z + f3.y*wc1.w;
                    }
                    a0 = 1.0f / (1.0f + expf(-(a0 + __ldg(brgb + 0))));
                    a1 = 1.0f / (1.0f + expf(-(a1 + __ldg(brgb + 1))));
                    a2 = 1.0f / (1.0f + expf(-(a2 + __ldg(brgb + 2))));
                    float* orow = out + ((size_t)tile * MTILE + r) * 3;
                    orow[0] = a0; orow[1] = a1; orow[2] = a2;
                }
            }
        }
    }
}

// ----------------------------------------------------------------------------
extern "C" void kernel_launch(void* const* d_in, const int* in_sizes, int n_in,
                              void* d_out, int out_size) {
    Params P;
    for (int i = 0; i < 32; i++) P.p[i] = (const float*)d_in[i];

    const int B = in_sizes[0] / 63;     // x is [B, 63]
    const int ntiles = B / MTILE;

    // prepass: weights -> fp16 padded row-major layout
    wconv_kernel<<<(WH_TOTAL + 255) / 256, 256>>>(P);

    cudaFuncSetAttribute(nerf_fused_fp16,
                         cudaFuncAttributeMaxDynamicSharedMemorySize, SMEM_TOTAL);

    int nsm = 148;
    cudaDeviceGetAttribute(&nsm, cudaDevAttrMultiProcessorCount, 0);
    int grid = (nsm < ntiles) ? nsm : ntiles;

    nerf_fused_fp16<<<grid, NTHREADS, SMEM_TOTAL>>>(P, (float*)d_out, ntiles, B);
}